// round 16
// baseline (speedup 1.0000x reference)
#include <cuda_runtime.h>
#include <cuda_bf16.h>
#include <math.h>

// ---------------- problem constants ----------------
#define BB 2
#define SS 64
#define LL 256
#define CC 192
#define C4 768
#define HH 4
#define DH 48
#define TT (BB*SS*LL)      // 32768 tokens
#define NBLK 6

// ---------------- scratch ----------------
__device__ float g_x[TT*CC];
__device__ float g_h[TT*CC];
__device__ float g_q[TT*CC];
__device__ float g_k[TT*CC];
__device__ float g_v[TT*CC];
__device__ float g_f1[TT*C4];
__device__ float2 g_stats[TT];

// pre-converted bf16 weights in mma-fragment order [mat][kt][ntile][lane]{uint2}
#define WQ_OFF 0
#define WK_OFF 110592
#define WV_OFF 221184
#define WO_OFF 331776
#define F1_OFF 442368
#define F2_OFF 663552
#define WB_TOTAL 884736
__device__ uint2 g_wb[WB_TOTAL];

__device__ __forceinline__ float elu1(float v) { return v > 0.0f ? v + 1.0f : expf(v); }
__device__ __forceinline__ float gelu_exact(float v) {
    return 0.5f * v * (1.0f + erff(v * 0.70710678118654752f));
}
__device__ __forceinline__ unsigned int packbf(float a, float b) {
    __nv_bfloat162 h = __floats2bfloat162_rn(a, b);
    return *(unsigned int*)&h;
}

// ============================================================
// Kernel 0: ALL weight conversion in ONE launch (range dispatch).
// dst idx (within family) = ((m*(K/16) + kt)*(N/8) + nt)*32 + lane
// ============================================================
__global__ void wconv_all_kernel(const float* __restrict__ wq, const float* __restrict__ wk,
                                 const float* __restrict__ wv, const float* __restrict__ wo,
                                 const float* __restrict__ f1, const float* __restrict__ f2,
                                 uint2* __restrict__ dst) {
    int tid = blockIdx.x * 256 + threadIdx.x;
    if (tid >= WB_TOTAL) return;
    const float* src; int off, N, K;
    if      (tid < WK_OFF) { src = wq; off = WQ_OFF; N = CC; K = CC; }
    else if (tid < WV_OFF) { src = wk; off = WK_OFF; N = CC; K = CC; }
    else if (tid < WO_OFF) { src = wv; off = WV_OFF; N = CC; K = CC; }
    else if (tid < F1_OFF) { src = wo; off = WO_OFF; N = CC; K = CC; }
    else if (tid < F2_OFF) { src = f1; off = F1_OFF; N = C4; K = CC; }
    else                   { src = f2; off = F2_OFF; N = CC; K = C4; }
    int loc  = tid - off;
    int lane = loc & 31;
    int rest = loc >> 5;
    int ntpr = N >> 3;
    int nt = rest % ntpr;
    int rest2 = rest / ntpr;
    int ktiles = K >> 4;
    int kt = rest2 % ktiles;
    int m  = rest2 / ktiles;
    int n  = nt * 8 + (lane >> 2);
    int p0 = lane & 3;
    const float* s = src + (size_t)m * N * K + (size_t)n * K + kt * 16;
    dst[tid] = make_uint2(packbf(s[2*p0],   s[2*p0+1]),
                          packbf(s[2*p0+8], s[2*p0+9]));
}

// ============================================================
// Kernel 1: embed + proj + rotary
// ============================================================
__global__ void embed_kernel(const int* __restrict__ tokens,
                             const float* __restrict__ emb,
                             const float* __restrict__ pw,
                             const float* __restrict__ pb,
                             float* __restrict__ out) {
    int t = blockIdx.x;
    int c = threadIdx.x;
    __shared__ float e[64];
    __shared__ float xv[CC];
    __shared__ float invf[96];
    if (c < 64) e[c] = emb[tokens[t] * 64 + c];
    if (c >= 64 && c < 160) {
        int j = c - 64;
        invf[j] = powf(10000.0f, -(float)j / 96.0f);
    }
    __syncthreads();
    float s = pb[c];
    const float* wr = pw + c * 64;
    #pragma unroll
    for (int i = 0; i < 64; i++) s += e[i] * wr[i];
    xv[c] = s;
    __syncthreads();
    int l = t & (LL - 1);
    int c2 = (c < 96) ? c : c - 96;
    float a = (float)l * invf[c2];
    float cs = cosf(a), sn = sinf(a);
    float rot = (c < 96) ? -xv[c + 96] : xv[c - 96];
    out[(size_t)t * CC + c] = s * cs + rot * sn;
}

// ============================================================
// Kernel 2: LN stats only — (mean, rstd) per token
// ============================================================
__global__ void ln_stats_kernel(const float* __restrict__ x,
                                float2* __restrict__ stats) {
    int t = blockIdx.x * 8 + threadIdx.y;
    int lane = threadIdx.x;
    const float* xr = x + (size_t)t * CC;
    float s = 0.f, ss = 0.f;
    #pragma unroll
    for (int i = 0; i < 6; i++) {
        float v = xr[lane + i * 32];
        s += v; ss += v * v;
    }
    #pragma unroll
    for (int o = 16; o; o >>= 1) {
        s  += __shfl_xor_sync(0xffffffffu, s, o);
        ss += __shfl_xor_sync(0xffffffffu, ss, o);
    }
    if (lane == 0) {
        float m   = s * (1.0f / CC);
        float var = ss * (1.0f / CC) - m * m;
        stats[t] = make_float2(m, rsqrtf(var + 1e-5f));
    }
}

// ============================================================
// bf16 GEMM (mma.m16n8k16), A staged via 3-stage smem pipeline
// (LDG distance 2: load it+2, stage it+1, compute it).
// B fragments loaded directly from pre-converted gmem (L1-resident).
// Block tile 128x96, 8 warps (4x2), warp tile 32x48 (2x6 mma).
// ============================================================
#define BM 128
#define BN 96
#define BK 16
#define ASZU 1024

__device__ __forceinline__ void gemm_stageA(
        unsigned int* As, const float4 aPre[2], int tid) {
    #pragma unroll
    for (int i = 0; i < 2; i++) {
        int lin = tid + i * 256;
        int m  = lin >> 2;
        int kq = (lin & 3) << 2;
        int mtile = m >> 4, r = m & 15;
        int gid = r & 7, rh = r >> 3;
        unsigned int p0 = packbf(aPre[i].x, aPre[i].y);
        unsigned int p1 = packbf(aPre[i].z, aPre[i].w);
        int pa = kq >> 1;
        int pb = pa + 1;
        As[mtile * 128 + (gid * 4 + (pa & 3)) * 4 + (rh + ((pa >> 2) << 1))] = p0;
        As[mtile * 128 + (gid * 4 + (pb & 3)) * 4 + (rh + ((pb >> 2) << 1))] = p1;
    }
}

template<bool LN>
__device__ __forceinline__ void gemm_body(
        const float* __restrict__ A, const uint2* __restrict__ Wb,
        const float* __restrict__ bias, float* __restrict__ Cout,
        int K, int N, int act, int accFlag, int rowBlk, int colBlk,
        unsigned int* AsBuf,
        const float2* __restrict__ stats,
        const float* __restrict__ lnG, const float* __restrict__ lnB) {
    int tid  = threadIdx.x;
    int lane = tid & 31;
    int warp = tid >> 5;
    int warpM = warp >> 1;
    int warpN = warp & 1;
    int gid = lane >> 2;
    int tig = lane & 3;
    int row0 = rowBlk * BM;
    int col0 = colBlk * BN;
    int ntpr = N >> 3;

    float acc[2][6][4];
    #pragma unroll
    for (int i = 0; i < 2; i++)
        #pragma unroll
        for (int j = 0; j < 6; j++)
            #pragma unroll
            for (int q = 0; q < 4; q++) acc[i][j][q] = 0.f;

    int aM0 = (tid) >> 2,       aK = (tid & 3) << 2;
    int aM1 = (tid + 256) >> 2;
    const float* aPtr0 = A + (size_t)(row0 + aM0) * K + aK;
    const float* aPtr1 = A + (size_t)(row0 + aM1) * K + aK;
    const uint2* wPtr = Wb + (size_t)(colBlk * 12 + warpN * 6) * 32 + lane;

    float2 st0, st1;
    if (LN) {
        st0 = stats[row0 + aM0];
        st1 = stats[row0 + aM1];
    }

    // LN-aware load of A tile `t` into regs
    auto loadA = [&](int t, float4 out2[2]) {
        int off = t * BK;
        out2[0] = *(const float4*)(aPtr0 + off);
        out2[1] = *(const float4*)(aPtr1 + off);
        if (LN) {
            int kb = off + aK;
            float4 g4 = *(const float4*)(lnG + kb);
            float4 b4 = *(const float4*)(lnB + kb);
            out2[0].x = (out2[0].x - st0.x) * st0.y * g4.x + b4.x;
            out2[0].y = (out2[0].y - st0.x) * st0.y * g4.y + b4.y;
            out2[0].z = (out2[0].z - st0.x) * st0.y * g4.z + b4.z;
            out2[0].w = (out2[0].w - st0.x) * st0.y * g4.w + b4.w;
            out2[1].x = (out2[1].x - st1.x) * st1.y * g4.x + b4.x;
            out2[1].y = (out2[1].y - st1.x) * st1.y * g4.y + b4.y;
            out2[1].z = (out2[1].z - st1.x) * st1.y * g4.z + b4.z;
            out2[1].w = (out2[1].w - st1.x) * st1.y * g4.w + b4.w;
        }
    };

    int NT = K / BK;
    float4 aCv[2], aLd[2];
    // prologue: tile 0 staged, tile 1 in regs
    loadA(0, aCv);
    gemm_stageA(AsBuf, aCv, tid);
    if (NT > 1) loadA(1, aCv);
    __syncthreads();

    int bufC = 0;   // buffer holding tile `it`
    for (int it = 0; it < NT; it++) {
        // issue LDG for tile it+2 (distance-2 prefetch)
        if (it + 2 < NT) loadA(it + 2, aLd);

        unsigned int* Ac = AsBuf + bufC * ASZU;
        {
            const uint2* wIter = wPtr + (size_t)it * ntpr * 32;
            uint2 bf[6];
            #pragma unroll
            for (int nt = 0; nt < 6; nt++) bf[nt] = wIter[nt * 32];
            uint4 af[2];
            #pragma unroll
            for (int mt = 0; mt < 2; mt++) {
                int mtile = warpM * 2 + mt;
                af[mt] = ((const uint4*)Ac)[mtile * 32 + lane];
            }
            #pragma unroll
            for (int mt = 0; mt < 2; mt++)
                #pragma unroll
                for (int nt = 0; nt < 6; nt++) {
                    asm volatile(
                        "mma.sync.aligned.m16n8k16.row.col.f32.bf16.bf16.f32 "
                        "{%0,%1,%2,%3}, {%4,%5,%6,%7}, {%8,%9}, {%0,%1,%2,%3};"
                        : "+f"(acc[mt][nt][0]), "+f"(acc[mt][nt][1]),
                          "+f"(acc[mt][nt][2]), "+f"(acc[mt][nt][3])
                        : "r"(af[mt].x), "r"(af[mt].y), "r"(af[mt].z), "r"(af[mt].w),
                          "r"(bf[nt].x), "r"(bf[nt].y));
                }
        }
        // stage tile it+1 (loaded last iter) into the third buffer
        if (it + 1 < NT) {
            int bufS = bufC + 1; if (bufS == 3) bufS = 0;
            gemm_stageA(AsBuf + bufS * ASZU, aCv, tid);
            __syncthreads();
            aCv[0] = aLd[0]; aCv[1] = aLd[1];
            bufC = bufS;
        }
    }

    #pragma unroll
    for (int mt = 0; mt < 2; mt++) {
        int r0 = row0 + warpM * 32 + mt * 16 + gid;
        #pragma unroll
        for (int nt = 0; nt < 6; nt++) {
            int c0 = col0 + warpN * 48 + nt * 8 + tig * 2;
            #pragma unroll
            for (int half = 0; half < 2; half++) {
                int r = r0 + half * 8;
                #pragma unroll
                for (int q = 0; q < 2; q++) {
                    int c = c0 + q;
                    float v = acc[mt][nt][half * 2 + q] + bias[c];
                    if (act == 1)      v = elu1(v) * 0.14433756729740643f;
                    else if (act == 2) v = elu1(v);
                    else if (act == 3) v = gelu_exact(v);
                    size_t idx = (size_t)r * N + c;
                    if (accFlag) v += Cout[idx];
                    Cout[idx] = v;
                }
            }
        }
    }
}

__global__ __launch_bounds__(256) void gemm_kernel(
        const float* __restrict__ A, const uint2* __restrict__ Wb,
        const float* __restrict__ bias, float* __restrict__ Cout,
        int K, int N, int act, int accFlag) {
    __shared__ unsigned int As[3 * ASZU];
    gemm_body<false>(A, Wb, bias, Cout, K, N, act, accFlag, blockIdx.x, blockIdx.y,
                     As, nullptr, nullptr, nullptr);
}

__global__ __launch_bounds__(256) void gemm_ln_kernel(
        const float* __restrict__ A, const uint2* __restrict__ Wb,
        const float* __restrict__ bias, float* __restrict__ Cout,
        int K, int N, int act, int accFlag,
        const float2* __restrict__ stats,
        const float* __restrict__ lnG, const float* __restrict__ lnB) {
    __shared__ unsigned int As[3 * ASZU];
    gemm_body<true>(A, Wb, bias, Cout, K, N, act, accFlag, blockIdx.x, blockIdx.y,
                    As, stats, lnG, lnB);
}

__global__ __launch_bounds__(256) void qkv_kernel(
        const float* __restrict__ A,
        const uint2* __restrict__ wqb, const uint2* __restrict__ wkb,
        const uint2* __restrict__ wvb,
        const float* __restrict__ bq, const float* __restrict__ bk, const float* __restrict__ bv,
        float* __restrict__ oq, float* __restrict__ ok, float* __restrict__ ov,
        const float2* __restrict__ stats,
        const float* __restrict__ lnG, const float* __restrict__ lnB) {
    __shared__ unsigned int As[3 * ASZU];
    int sel = blockIdx.y >> 1;
    int cb  = blockIdx.y & 1;
    const uint2* W  = sel == 0 ? wqb : (sel == 1 ? wkb : wvb);
    const float* bi = sel == 0 ? bq : (sel == 1 ? bk : bv);
    float* Cout     = sel == 0 ? oq : (sel == 1 ? ok : ov);
    int act         = sel == 0 ? 1  : (sel == 1 ? 2  : 0);
    gemm_body<true>(A, W, bi, Cout, CC, CC, act, 0, blockIdx.x, cb,
                    As, stats, lnG, lnB);
}

// ============================================================
// Kernel 4: linear attention (unchanged from R11/R12 win)
// ============================================================
__global__ __launch_bounds__(256) void attn_kernel(
        const float* __restrict__ q, const float* __restrict__ k,
        const float* __restrict__ v, float* __restrict__ o,
        int N, int isCol) {
    extern __shared__ float sm[];
    float* ks   = sm;
    float* vs   = ks + N * DH;
    float* kv   = vs + N * DH;
    float* psum = kv + DH * DH;
    float* ksum = psum + 2 * DH;
    float* zz   = ksum + DH;
    int g = blockIdx.x, h = blockIdx.y;
    int tid = threadIdx.x;

    for (int lin = tid; lin < N * 12; lin += 256) {
        int n = lin / 12;
        int j = lin - n * 12;
        int t = isCol ? ((((g >> 8) * SS + n) << 8) + (g & 255)) : g * N + n;
        size_t base = (size_t)t * CC + h * DH + j * 4;
        ((float4*)ks)[lin] = *(const float4*)(k + base);
        ((float4*)vs)[lin] = *(const float4*)(v + base);
    }
    __syncthreads();

    if (tid < 72) {
        int dp = tid % 12;
        int eo = tid / 12;
        float acc[4][8];
        #pragma unroll
        for (int i = 0; i < 4; i++)
            #pragma unroll
            for (int j = 0; j < 8; j++) acc[i][j] = 0.f;
        for (int n = 0; n < N; n++) {
            float4 kk = ((const float4*)ks)[n * 12 + dp];
            float4 va = ((const float4*)vs)[n * 12 + eo * 2];
            float4 vb = ((const float4*)vs)[n * 12 + eo * 2 + 1];
            float kr[4] = {kk.x, kk.y, kk.z, kk.w};
            float vv[8] = {va.x, va.y, va.z, va.w, vb.x, vb.y, vb.z, vb.w};
            #pragma unroll
            for (int i = 0; i < 4; i++)
                #pragma unroll
                for (int j = 0; j < 8; j++) acc[i][j] += kr[i] * vv[j];
        }
        #pragma unroll
        for (int i = 0; i < 4; i++) {
            ((float4*)kv)[(dp * 4 + i) * 12 + eo * 2]     =
                make_float4(acc[i][0], acc[i][1], acc[i][2], acc[i][3]);
            ((float4*)kv)[(dp * 4 + i) * 12 + eo * 2 + 1] =
                make_float4(acc[i][4], acc[i][5], acc[i][6], acc[i][7]);
        }
    } else if (tid >= 96 && tid < 192) {
        int idx = tid - 96;
        int d  = idx % DH;
        int ch = idx / DH;
        int half = N >> 1;
        int n0 = ch * half;
        float s = 0.f;
        for (int n = n0; n < n0 + half; n++) s += ks[n * DH + d];
        psum[ch * DH + d] = s;
    }
    __syncthreads();

    if (tid < DH) ksum[tid] = psum[tid] + psum[DH + tid];
    __syncthreads();

    if (tid < N) {
        int n = tid;
        int t = isCol ? ((((g >> 8) * SS + n) << 8) + (g & 255)) : g * N + n;
        const float* qp = q + (size_t)t * CC + h * DH;
        float s = 0.f;
        #pragma unroll
        for (int j = 0; j < 12; j++) {
            float4 f = *(const float4*)(qp + j * 4);
            s += f.x * ksum[j*4] + f.y * ksum[j*4+1] + f.z * ksum[j*4+2] + f.w * ksum[j*4+3];
        }
        zz[n] = 1.0f / (s + 1e-6f);
    }
    __syncthreads();

    int items = (N >> 2) * 6;
    for (int item = tid; item < items; item += 256) {
        int np = item / 6, eo = item % 6;
        int n0 = np * 4;
        const float* qp[4];
        int tt[4];
        #pragma unroll
        for (int i = 0; i < 4; i++) {
            int n = n0 + i;
            tt[i] = isCol ? ((((g >> 8) * SS + n) << 8) + (g & 255)) : g * N + n;
            qp[i] = q + (size_t)tt[i] * CC + h * DH;
        }
        float acc[4][8];
        #pragma unroll
        for (int i = 0; i < 4; i++)
            #pragma unroll
            for (int j = 0; j < 8; j++) acc[i][j] = 0.f;

        for (int j = 0; j < 12; j++) {
            float qr[4][4];
            #pragma unroll
            for (int i = 0; i < 4; i++) {
                float4 f = *(const float4*)(qp[i] + j * 4);
                qr[i][0] = f.x; qr[i][1] = f.y; qr[i][2] = f.z; qr[i][3] = f.w;
            }
            #pragma unroll
            for (int dd = 0; dd < 4; dd++) {
                int d = j * 4 + dd;
                float4 a = ((const float4*)kv)[d * 12 + eo * 2];
                float4 b = ((const float4*)kv)[d * 12 + eo * 2 + 1];
                #pragma unroll
                for (int i = 0; i < 4; i++) {
                    float qd = qr[i][dd];
                    acc[i][0] += qd * a.x; acc[i][1] += qd * a.y;
                    acc[i][2] += qd * a.z; acc[i][3] += qd * a.w;
                    acc[i][4] += qd * b.x; acc[i][5] += qd * b.y;
                    acc[i][6] += qd * b.z; acc[i][7] += qd * b.w;
                }
            }
        }
        #pragma unroll
        for (int i = 0; i < 4; i++) {
            float z = zz[n0 + i];
            float* op = o + (size_t)tt[i] * CC + h * DH + eo * 8;
            *(float4*)op       = make_float4(acc[i][0]*z, acc[i][1]*z, acc[i][2]*z, acc[i][3]*z);
            *(float4*)(op + 4) = make_float4(acc[i][4]*z, acc[i][5]*z, acc[i][6]*z, acc[i][7]*z);
        }
    }
}

// ============================================================
// Kernel 5: head
// ============================================================
__global__ void final_kernel(const float* __restrict__ x,
                             const float* __restrict__ pw,
                             const float* __restrict__ pb,
                             float* __restrict__ out) {
    int t = blockIdx.x * 8 + threadIdx.y;
    int lane = threadIdx.x;
    const float* xr = x + (size_t)t * CC;
    float s = 0.f;
    #pragma unroll
    for (int i = 0; i < 6; i++) {
        int c = lane + i * 32;
        s += xr[c] * pw[c];
    }
    #pragma unroll
    for (int o = 16; o; o >>= 1) s += __shfl_xor_sync(0xffffffffu, s, o);
    if (lane == 0) {
        float ov = s + pb[0];
        float sp = (ov > 20.f) ? ov : log1pf(expf(ov));
        out[t] = 1.0f / (1.0f + expf(-sp));
    }
}

// ============================================================
// Host orchestration
// ============================================================
extern "C" void kernel_launch(void* const* d_in, const int* in_sizes, int n_in,
                              void* d_out, int out_size) {
    const int*   tokens = (const int*)  d_in[0];
    const float* emb    = (const float*)d_in[1];
    const float* proj_w = (const float*)d_in[2];
    const float* proj_b = (const float*)d_in[3];
    const float* ln_g   = (const float*)d_in[4];
    const float* ln_b   = (const float*)d_in[5];
    const float* wq     = (const float*)d_in[6];
    const float* wk     = (const float*)d_in[7];
    const float* wv     = (const float*)d_in[8];
    const float* wo     = (const float*)d_in[9];
    const float* bq     = (const float*)d_in[10];
    const float* bk     = (const float*)d_in[11];
    const float* bv     = (const float*)d_in[12];
    const float* bo     = (const float*)d_in[13];
    const float* ffn_w1 = (const float*)d_in[14];
    const float* ffn_b1 = (const float*)d_in[15];
    const float* ffn_w2 = (const float*)d_in[16];
    const float* ffn_b2 = (const float*)d_in[17];
    const float* pw_w   = (const float*)d_in[18];
    const float* pw_b   = (const float*)d_in[19];
    float* out = (float*)d_out;

    float *px, *ph, *pq, *pk, *pv, *pf;
    float2* pst;
    uint2* pwb;
    cudaGetSymbolAddress((void**)&px, g_x);
    cudaGetSymbolAddress((void**)&ph, g_h);
    cudaGetSymbolAddress((void**)&pq, g_q);
    cudaGetSymbolAddress((void**)&pk, g_k);
    cudaGetSymbolAddress((void**)&pv, g_v);
    cudaGetSymbolAddress((void**)&pf, g_f1);
    cudaGetSymbolAddress((void**)&pst, g_stats);
    cudaGetSymbolAddress((void**)&pwb, g_wb);

    size_t smemRow = (size_t)(2 * LL * DH + DH * DH + 3 * DH + LL) * sizeof(float);
    size_t smemCol = (size_t)(2 * SS * DH + DH * DH + 3 * DH + SS) * sizeof(float);
    cudaFuncSetAttribute(attn_kernel, cudaFuncAttributeMaxDynamicSharedMemorySize, 112640);

    // single fused weight conversion
    wconv_all_kernel<<<(WB_TOTAL + 255) / 256, 256>>>(wq, wk, wv, wo, ffn_w1, ffn_w2, pwb);

    const int MAT_ATT = (CC/16) * (CC/8) * 32;
    const int MAT_F   = 36864;

    dim3 lnBlk(32, 8);
    dim3 gQKV(TT / BM, 6);
    dim3 g192(TT / BM, CC / BN);
    dim3 g768(TT / BM, C4 / BN);

    embed_kernel<<<TT, CC>>>(tokens, emb, proj_w, proj_b, px);

    for (int i = 0; i < NBLK; i++) {
        for (int dir = 0; dir < 2; dir++) {
            const float* lg = ln_g + (size_t)(i * 3 + dir) * CC;
            const float* lb = ln_b + (size_t)(i * 3 + dir) * CC;
            ln_stats_kernel<<<TT / 8, lnBlk>>>(px, pst);

            int mi = i * 2 + dir;
            size_t boff = (size_t)mi * CC;
            qkv_kernel<<<gQKV, 256>>>(px,
                                      pwb + WQ_OFF + (size_t)mi * MAT_ATT,
                                      pwb + WK_OFF + (size_t)mi * MAT_ATT,
                                      pwb + WV_OFF + (size_t)mi * MAT_ATT,
                                      bq + boff, bk + boff, bv + boff,
                                      pq, pk, pv, pst, lg, lb);

            if (dir == 0) {
                attn_kernel<<<dim3(BB * SS, HH), 256, smemRow>>>(pq, pk, pv, ph, LL, 0);
            } else {
                attn_kernel<<<dim3(BB * LL, HH), 256, smemCol>>>(pq, pk, pv, ph, SS, 1);
            }

            gemm_kernel<<<g192, 256>>>(ph, pwb + WO_OFF + (size_t)mi * MAT_ATT,
                                       bo + boff, px, CC, CC, 0, 1);
        }
        const float* lg = ln_g + (size_t)(i * 3 + 2) * CC;
        const float* lb = ln_b + (size_t)(i * 3 + 2) * CC;
        ln_stats_kernel<<<TT / 8, lnBlk>>>(px, pst);
        gemm_ln_kernel<<<g768, 256>>>(px, pwb + F1_OFF + (size_t)i * MAT_F,
                                      ffn_b1 + (size_t)i * C4,
                                      pf, CC, C4, 3, 0, pst, lg, lb);
        gemm_kernel<<<g192, 256>>>(pf, pwb + F2_OFF + (size_t)i * MAT_F,
                                   ffn_b2 + (size_t)i * CC,
                                   px, C4, CC, 0, 1);
    }

    final_kernel<<<TT / 8, lnBlk>>>(px, pw_w, pw_b, out);
}

// round 17
// speedup vs baseline: 1.2037x; 1.2037x over previous
#include <cuda_runtime.h>
#include <cuda_bf16.h>
#include <math.h>

// ---------------- problem constants ----------------
#define BB 2
#define SS 64
#define LL 256
#define CC 192
#define C4 768
#define HH 4
#define DH 48
#define TT (BB*SS*LL)      // 32768 tokens
#define NBLK 6

// ---------------- scratch ----------------
__device__ float g_x[TT*CC];
__device__ float g_h[TT*CC];
__device__ float g_q[TT*CC];
__device__ float g_k[TT*CC];
__device__ float g_v[TT*CC];
__device__ float g_f1[TT*C4];
__device__ float2 g_stats[TT];   // per-token (mean, rstd)

__device__ __forceinline__ float elu1(float v) { return v > 0.0f ? v + 1.0f : expf(v); }
__device__ __forceinline__ float gelu_exact(float v) {
    return 0.5f * v * (1.0f + erff(v * 0.70710678118654752f));
}
__device__ __forceinline__ unsigned int packbf(float a, float b) {
    __nv_bfloat162 h = __floats2bfloat162_rn(a, b);
    return *(unsigned int*)&h;
}

// ============================================================
// Kernel 1: embed + proj + rotary
// ============================================================
__global__ void embed_kernel(const int* __restrict__ tokens,
                             const float* __restrict__ emb,
                             const float* __restrict__ pw,
                             const float* __restrict__ pb,
                             float* __restrict__ out) {
    int t = blockIdx.x;
    int c = threadIdx.x;
    __shared__ float e[64];
    __shared__ float xv[CC];
    __shared__ float invf[96];
    if (c < 64) e[c] = emb[tokens[t] * 64 + c];
    if (c >= 64 && c < 160) {
        int j = c - 64;
        invf[j] = powf(10000.0f, -(float)j / 96.0f);
    }
    __syncthreads();
    float s = pb[c];
    const float* wr = pw + c * 64;
    #pragma unroll
    for (int i = 0; i < 64; i++) s += e[i] * wr[i];
    xv[c] = s;
    __syncthreads();
    int l = t & (LL - 1);
    int c2 = (c < 96) ? c : c - 96;
    float a = (float)l * invf[c2];
    float cs = cosf(a), sn = sinf(a);
    float rot = (c < 96) ? -xv[c + 96] : xv[c - 96];
    out[(size_t)t * CC + c] = s * cs + rot * sn;
}

// ============================================================
// Kernel 2: LN stats only — (mean, rstd) per token
// ============================================================
__global__ void ln_stats_kernel(const float* __restrict__ x,
                                float2* __restrict__ stats) {
    int t = blockIdx.x * 8 + threadIdx.y;
    int lane = threadIdx.x;
    const float* xr = x + (size_t)t * CC;
    float s = 0.f, ss = 0.f;
    #pragma unroll
    for (int i = 0; i < 6; i++) {
        float v = xr[lane + i * 32];
        s += v; ss += v * v;
    }
    #pragma unroll
    for (int o = 16; o; o >>= 1) {
        s  += __shfl_xor_sync(0xffffffffu, s, o);
        ss += __shfl_xor_sync(0xffffffffu, ss, o);
    }
    if (lane == 0) {
        float m   = s * (1.0f / CC);
        float var = ss * (1.0f / CC) - m * m;
        stats[t] = make_float2(m, rsqrtf(var + 1e-5f));
    }
}

// ============================================================
// bf16 tensor-core GEMM (mma.m16n8k16, fp32 accum) — R14 design restored.
// Fragment-major smem, 2-buffer ping-pong, ONE barrier per k-tile,
// optional fused LN on the A path. Block 128x96, 8 warps, warp 32x48.
// ============================================================
#define BM 128
#define BN 96
#define BK 16
#define ASZU 1024
#define BSZU 768

__device__ __forceinline__ void gemm_stage_bf16(
        unsigned int* As, unsigned int* Bs,
        const float4 aPre[2], const float4 bPre[2], int tid) {
    #pragma unroll
    for (int i = 0; i < 2; i++) {
        int lin = tid + i * 256;
        int m  = lin >> 2;
        int kq = (lin & 3) << 2;             // 0,4,8,12
        int mtile = m >> 4, r = m & 15;
        int gid = r & 7, rh = r >> 3;
        unsigned int p0 = packbf(aPre[i].x, aPre[i].y);
        unsigned int p1 = packbf(aPre[i].z, aPre[i].w);
        int pa = kq >> 1;                    // 0,2,4,6
        int pb = pa + 1;
        As[mtile * 128 + (gid * 4 + (pa & 3)) * 4 + (rh + ((pa >> 2) << 1))] = p0;
        As[mtile * 128 + (gid * 4 + (pb & 3)) * 4 + (rh + ((pb >> 2) << 1))] = p1;
    }
    #pragma unroll
    for (int i = 0; i < 2; i++) {
        int lin = tid + i * 256;
        if (lin < BN * 4) {
            int n  = lin >> 2;
            int kq = (lin & 3) << 2;
            int ntile = n >> 3, c = n & 7;
            unsigned int p0 = packbf(bPre[i].x, bPre[i].y);
            unsigned int p1 = packbf(bPre[i].z, bPre[i].w);
            int pa = kq >> 1, pb = pa + 1;
            Bs[ntile * 64 + (c * 4 + (pa & 3)) * 2 + (pa >> 2)] = p0;
            Bs[ntile * 64 + (c * 4 + (pb & 3)) * 2 + (pb >> 2)] = p1;
        }
    }
}

template<bool LN>
__device__ __forceinline__ void gemm_body(
        const float* __restrict__ A, const float* __restrict__ W,
        const float* __restrict__ bias, float* __restrict__ Cout,
        int K, int N, int act, int accFlag, int rowBlk, int colBlk,
        unsigned int* AsBuf, unsigned int* BsBuf,
        const float2* __restrict__ stats,
        const float* __restrict__ lnG, const float* __restrict__ lnB) {
    int tid  = threadIdx.x;
    int lane = tid & 31;
    int warp = tid >> 5;
    int warpM = warp >> 1;
    int warpN = warp & 1;
    int gid = lane >> 2;
    int tig = lane & 3;
    int row0 = rowBlk * BM;
    int col0 = colBlk * BN;

    float acc[2][6][4];
    #pragma unroll
    for (int i = 0; i < 2; i++)
        #pragma unroll
        for (int j = 0; j < 6; j++)
            #pragma unroll
            for (int q = 0; q < 4; q++) acc[i][j][q] = 0.f;

    int aM0 = (tid) >> 2,       aK = (tid & 3) << 2;
    int aM1 = (tid + 256) >> 2;
    int bN0 = tid >> 2,         bK = (tid & 3) << 2;
    int bN1 = (tid + 256) >> 2;
    const float* aPtr0 = A + (size_t)(row0 + aM0) * K + aK;
    const float* aPtr1 = A + (size_t)(row0 + aM1) * K + aK;
    const float* bPtr0 = W + (size_t)(col0 + bN0) * K + bK;
    const float* bPtr1 = W + (size_t)(col0 + (bN1 < BN ? bN1 : 0)) * K + bK;
    bool bHas1 = (tid < (BN * 4 - 256));

    float2 st0, st1;
    if (LN) {
        st0 = stats[row0 + aM0];
        st1 = stats[row0 + aM1];
    }

    float4 aPre[2]; float4 bPre[2];
    aPre[0] = *(const float4*)aPtr0;
    aPre[1] = *(const float4*)aPtr1;
    bPre[0] = *(const float4*)bPtr0;
    bPre[1] = bHas1 ? *(const float4*)bPtr1 : make_float4(0.f,0.f,0.f,0.f);
    if (LN) {
        float4 g4 = *(const float4*)(lnG + aK);
        float4 b4 = *(const float4*)(lnB + aK);
        aPre[0].x = (aPre[0].x - st0.x) * st0.y * g4.x + b4.x;
        aPre[0].y = (aPre[0].y - st0.x) * st0.y * g4.y + b4.y;
        aPre[0].z = (aPre[0].z - st0.x) * st0.y * g4.z + b4.z;
        aPre[0].w = (aPre[0].w - st0.x) * st0.y * g4.w + b4.w;
        aPre[1].x = (aPre[1].x - st1.x) * st1.y * g4.x + b4.x;
        aPre[1].y = (aPre[1].y - st1.x) * st1.y * g4.y + b4.y;
        aPre[1].z = (aPre[1].z - st1.x) * st1.y * g4.z + b4.z;
        aPre[1].w = (aPre[1].w - st1.x) * st1.y * g4.w + b4.w;
    }

    int NT = K / BK;
    gemm_stage_bf16(AsBuf, BsBuf, aPre, bPre, tid);
    __syncthreads();

    for (int it = 0; it < NT; it++) {
        int cur = it & 1;
        if (it + 1 < NT) {
            int off = (it + 1) * BK;
            aPre[0] = *(const float4*)(aPtr0 + off);
            aPre[1] = *(const float4*)(aPtr1 + off);
            bPre[0] = *(const float4*)(bPtr0 + off);
            if (bHas1) bPre[1] = *(const float4*)(bPtr1 + off);
            if (LN) {
                int kb = off + aK;
                float4 g4 = *(const float4*)(lnG + kb);
                float4 b4 = *(const float4*)(lnB + kb);
                aPre[0].x = (aPre[0].x - st0.x) * st0.y * g4.x + b4.x;
                aPre[0].y = (aPre[0].y - st0.x) * st0.y * g4.y + b4.y;
                aPre[0].z = (aPre[0].z - st0.x) * st0.y * g4.z + b4.z;
                aPre[0].w = (aPre[0].w - st0.x) * st0.y * g4.w + b4.w;
                aPre[1].x = (aPre[1].x - st1.x) * st1.y * g4.x + b4.x;
                aPre[1].y = (aPre[1].y - st1.x) * st1.y * g4.y + b4.y;
                aPre[1].z = (aPre[1].z - st1.x) * st1.y * g4.z + b4.z;
                aPre[1].w = (aPre[1].w - st1.x) * st1.y * g4.w + b4.w;
            }
        }
        unsigned int* Ac = AsBuf + cur * ASZU;
        unsigned int* Bc = BsBuf + cur * BSZU;
        {
            uint4 af[2]; uint2 bf[6];
            #pragma unroll
            for (int mt = 0; mt < 2; mt++) {
                int mtile = warpM * 2 + mt;
                af[mt] = ((const uint4*)Ac)[mtile * 32 + lane];
            }
            #pragma unroll
            for (int nt = 0; nt < 6; nt++) {
                int ntile = warpN * 6 + nt;
                bf[nt] = ((const uint2*)Bc)[ntile * 32 + lane];
            }
            #pragma unroll
            for (int mt = 0; mt < 2; mt++)
                #pragma unroll
                for (int nt = 0; nt < 6; nt++) {
                    asm volatile(
                        "mma.sync.aligned.m16n8k16.row.col.f32.bf16.bf16.f32 "
                        "{%0,%1,%2,%3}, {%4,%5,%6,%7}, {%8,%9}, {%0,%1,%2,%3};"
                        : "+f"(acc[mt][nt][0]), "+f"(acc[mt][nt][1]),
                          "+f"(acc[mt][nt][2]), "+f"(acc[mt][nt][3])
                        : "r"(af[mt].x), "r"(af[mt].y), "r"(af[mt].z), "r"(af[mt].w),
                          "r"(bf[nt].x), "r"(bf[nt].y));
                }
        }
        if (it + 1 < NT) {
            gemm_stage_bf16(AsBuf + (cur ^ 1) * ASZU, BsBuf + (cur ^ 1) * BSZU,
                            aPre, bPre, tid);
            __syncthreads();
        }
    }

    #pragma unroll
    for (int mt = 0; mt < 2; mt++) {
        int r0 = row0 + warpM * 32 + mt * 16 + gid;
        #pragma unroll
        for (int nt = 0; nt < 6; nt++) {
            int c0 = col0 + warpN * 48 + nt * 8 + tig * 2;
            #pragma unroll
            for (int half = 0; half < 2; half++) {
                int r = r0 + half * 8;
                #pragma unroll
                for (int q = 0; q < 2; q++) {
                    int c = c0 + q;
                    float v = acc[mt][nt][half * 2 + q] + bias[c];
                    if (act == 1)      v = elu1(v) * 0.14433756729740643f;
                    else if (act == 2) v = elu1(v);
                    else if (act == 3) v = gelu_exact(v);
                    size_t idx = (size_t)r * N + c;
                    if (accFlag) v += Cout[idx];
                    Cout[idx] = v;
                }
            }
        }
    }
}

__global__ __launch_bounds__(256) void gemm_kernel(
        const float* __restrict__ A, const float* __restrict__ W,
        const float* __restrict__ bias, float* __restrict__ Cout,
        int K, int N, int act, int accFlag) {
    __shared__ unsigned int As[2 * ASZU];
    __shared__ unsigned int Bs[2 * BSZU];
    gemm_body<false>(A, W, bias, Cout, K, N, act, accFlag, blockIdx.x, blockIdx.y,
                     As, Bs, nullptr, nullptr, nullptr);
}

__global__ __launch_bounds__(256) void gemm_ln_kernel(
        const float* __restrict__ A, const float* __restrict__ W,
        const float* __restrict__ bias, float* __restrict__ Cout,
        int K, int N, int act, int accFlag,
        const float2* __restrict__ stats,
        const float* __restrict__ lnG, const float* __restrict__ lnB) {
    __shared__ unsigned int As[2 * ASZU];
    __shared__ unsigned int Bs[2 * BSZU];
    gemm_body<true>(A, W, bias, Cout, K, N, act, accFlag, blockIdx.x, blockIdx.y,
                    As, Bs, stats, lnG, lnB);
}

__global__ __launch_bounds__(256) void qkv_kernel(
        const float* __restrict__ A,
        const float* __restrict__ wq, const float* __restrict__ wk, const float* __restrict__ wv,
        const float* __restrict__ bq, const float* __restrict__ bk, const float* __restrict__ bv,
        float* __restrict__ oq, float* __restrict__ ok, float* __restrict__ ov,
        const float2* __restrict__ stats,
        const float* __restrict__ lnG, const float* __restrict__ lnB) {
    __shared__ unsigned int As[2 * ASZU];
    __shared__ unsigned int Bs[2 * BSZU];
    int sel = blockIdx.y >> 1;
    int cb  = blockIdx.y & 1;
    const float* W  = sel == 0 ? wq : (sel == 1 ? wk : wv);
    const float* bi = sel == 0 ? bq : (sel == 1 ? bk : bv);
    float* Cout     = sel == 0 ? oq : (sel == 1 ? ok : ov);
    int act         = sel == 0 ? 1  : (sel == 1 ? 2  : 0);
    gemm_body<true>(A, W, bi, Cout, CC, CC, act, 0, blockIdx.x, cb,
                    As, Bs, stats, lnG, lnB);
}

// ============================================================
// Kernel 4: linear attention — kv phase split across 2 thread groups:
// threads 0..143 each accumulate a 4d x 8e tile over HALF of N in regs
// (serial length N/2); threads 144..239 do ksum partials concurrently.
// Combine: half-1 stores, half-0 adds. One extra barrier, no extra smem.
// ============================================================
__global__ __launch_bounds__(256) void attn_kernel(
        const float* __restrict__ q, const float* __restrict__ k,
        const float* __restrict__ v, float* __restrict__ o,
        int N, int isCol) {
    extern __shared__ float sm[];
    float* ks   = sm;                    // N*48
    float* vs   = ks + N * DH;           // N*48
    float* kv   = vs + N * DH;           // 48*48
    float* psum = kv + DH * DH;          // 2*48
    float* ksum = psum + 2 * DH;         // 48
    float* zz   = ksum + DH;             // N
    int g = blockIdx.x, h = blockIdx.y;
    int tid = threadIdx.x;

    // ---- stage k, v ----
    for (int lin = tid; lin < N * 12; lin += 256) {
        int n = lin / 12;
        int j = lin - n * 12;
        int t = isCol ? ((((g >> 8) * SS + n) << 8) + (g & 255)) : g * N + n;
        size_t base = (size_t)t * CC + h * DH + j * 4;
        ((float4*)ks)[lin] = *(const float4*)(k + base);
        ((float4*)vs)[lin] = *(const float4*)(v + base);
    }
    __syncthreads();

    // ---- kv partials (0..143) and ksum partials (144..239) ----
    float acc[4][8];
    int dp = 0, eo = 0;
    if (tid < 144) {
        int halfsel = tid >= 72 ? 1 : 0;
        int loc = tid - halfsel * 72;
        dp = loc % 12;       // d block of 4
        eo = loc / 12;       // e block of 8
        #pragma unroll
        for (int i = 0; i < 4; i++)
            #pragma unroll
            for (int j = 0; j < 8; j++) acc[i][j] = 0.f;
        int n0 = halfsel * (N >> 1);
        int n1 = n0 + (N >> 1);
        for (int n = n0; n < n1; n++) {
            float4 kk = ((const float4*)ks)[n * 12 + dp];
            float4 va = ((const float4*)vs)[n * 12 + eo * 2];
            float4 vb = ((const float4*)vs)[n * 12 + eo * 2 + 1];
            float kr[4] = {kk.x, kk.y, kk.z, kk.w};
            float vv[8] = {va.x, va.y, va.z, va.w, vb.x, vb.y, vb.z, vb.w};
            #pragma unroll
            for (int i = 0; i < 4; i++)
                #pragma unroll
                for (int j = 0; j < 8; j++) acc[i][j] += kr[i] * vv[j];
        }
    } else if (tid < 240) {
        int idx = tid - 144;
        int d  = idx % DH;
        int ch = idx / DH;
        int half = N >> 1;
        int n0 = ch * half;
        float s = 0.f;
        for (int n = n0; n < n0 + half; n++) s += ks[n * DH + d];
        psum[ch * DH + d] = s;
    }
    __syncthreads();

    // half-1 stores its partial; ksum reduced in the same window
    if (tid >= 72 && tid < 144) {
        #pragma unroll
        for (int i = 0; i < 4; i++) {
            ((float4*)kv)[(dp * 4 + i) * 12 + eo * 2]     =
                make_float4(acc[i][0], acc[i][1], acc[i][2], acc[i][3]);
            ((float4*)kv)[(dp * 4 + i) * 12 + eo * 2 + 1] =
                make_float4(acc[i][4], acc[i][5], acc[i][6], acc[i][7]);
        }
    }
    if (tid < DH) ksum[tid] = psum[tid] + psum[DH + tid];
    __syncthreads();

    // half-0 adds its partial; z computed concurrently (needs only ksum)
    if (tid < 72) {
        #pragma unroll
        for (int i = 0; i < 4; i++) {
            float4 a = ((const float4*)kv)[(dp * 4 + i) * 12 + eo * 2];
            float4 b = ((const float4*)kv)[(dp * 4 + i) * 12 + eo * 2 + 1];
            ((float4*)kv)[(dp * 4 + i) * 12 + eo * 2] =
                make_float4(a.x + acc[i][0], a.y + acc[i][1], a.z + acc[i][2], a.w + acc[i][3]);
            ((float4*)kv)[(dp * 4 + i) * 12 + eo * 2 + 1] =
                make_float4(b.x + acc[i][4], b.y + acc[i][5], b.z + acc[i][6], b.w + acc[i][7]);
        }
    }
    if (tid < N) {
        int n = tid;
        int t = isCol ? ((((g >> 8) * SS + n) << 8) + (g & 255)) : g * N + n;
        const float* qp = q + (size_t)t * CC + h * DH;
        float s = 0.f;
        #pragma unroll
        for (int j = 0; j < 12; j++) {
            float4 f = *(const float4*)(qp + j * 4);
            s += f.x * ksum[j*4] + f.y * ksum[j*4+1] + f.z * ksum[j*4+2] + f.w * ksum[j*4+3];
        }
        zz[n] = 1.0f / (s + 1e-6f);
    }
    __syncthreads();

    // ---- out: 4n x 8e tiles, d-vectorized ----
    int items = (N >> 2) * 6;
    for (int item = tid; item < items; item += 256) {
        int np = item / 6, eo2 = item % 6;
        int n0 = np * 4;
        const float* qp[4];
        int tt[4];
        #pragma unroll
        for (int i = 0; i < 4; i++) {
            int n = n0 + i;
            tt[i] = isCol ? ((((g >> 8) * SS + n) << 8) + (g & 255)) : g * N + n;
            qp[i] = q + (size_t)tt[i] * CC + h * DH;
        }
        float acc2[4][8];
        #pragma unroll
        for (int i = 0; i < 4; i++)
            #pragma unroll
            for (int j = 0; j < 8; j++) acc2[i][j] = 0.f;

        for (int j = 0; j < 12; j++) {
            float qr[4][4];
            #pragma unroll
            for (int i = 0; i < 4; i++) {
                float4 f = *(const float4*)(qp[i] + j * 4);
                qr[i][0] = f.x; qr[i][1] = f.y; qr[i][2] = f.z; qr[i][3] = f.w;
            }
            #pragma unroll
            for (int dd = 0; dd < 4; dd++) {
                int d = j * 4 + dd;
                float4 a = ((const float4*)kv)[d * 12 + eo2 * 2];
                float4 b = ((const float4*)kv)[d * 12 + eo2 * 2 + 1];
                #pragma unroll
                for (int i = 0; i < 4; i++) {
                    float qd = qr[i][dd];
                    acc2[i][0] += qd * a.x; acc2[i][1] += qd * a.y;
                    acc2[i][2] += qd * a.z; acc2[i][3] += qd * a.w;
                    acc2[i][4] += qd * b.x; acc2[i][5] += qd * b.y;
                    acc2[i][6] += qd * b.z; acc2[i][7] += qd * b.w;
                }
            }
        }
        #pragma unroll
        for (int i = 0; i < 4; i++) {
            float z = zz[n0 + i];
            float* op = o + (size_t)tt[i] * CC + h * DH + eo2 * 8;
            *(float4*)op       = make_float4(acc2[i][0]*z, acc2[i][1]*z, acc2[i][2]*z, acc2[i][3]*z);
            *(float4*)(op + 4) = make_float4(acc2[i][4]*z, acc2[i][5]*z, acc2[i][6]*z, acc2[i][7]*z);
        }
    }
}

// ============================================================
// Kernel 5: head
// ============================================================
__global__ void final_kernel(const float* __restrict__ x,
                             const float* __restrict__ pw,
                             const float* __restrict__ pb,
                             float* __restrict__ out) {
    int t = blockIdx.x * 8 + threadIdx.y;
    int lane = threadIdx.x;
    const float* xr = x + (size_t)t * CC;
    float s = 0.f;
    #pragma unroll
    for (int i = 0; i < 6; i++) {
        int c = lane + i * 32;
        s += xr[c] * pw[c];
    }
    #pragma unroll
    for (int o = 16; o; o >>= 1) s += __shfl_xor_sync(0xffffffffu, s, o);
    if (lane == 0) {
        float ov = s + pb[0];
        float sp = (ov > 20.f) ? ov : log1pf(expf(ov));
        out[t] = 1.0f / (1.0f + expf(-sp));
    }
}

// ============================================================
// Host orchestration
// ============================================================
extern "C" void kernel_launch(void* const* d_in, const int* in_sizes, int n_in,
                              void* d_out, int out_size) {
    const int*   tokens = (const int*)  d_in[0];
    const float* emb    = (const float*)d_in[1];
    const float* proj_w = (const float*)d_in[2];
    const float* proj_b = (const float*)d_in[3];
    const float* ln_g   = (const float*)d_in[4];
    const float* ln_b   = (const float*)d_in[5];
    const float* wq     = (const float*)d_in[6];
    const float* wk     = (const float*)d_in[7];
    const float* wv     = (const float*)d_in[8];
    const float* wo     = (const float*)d_in[9];
    const float* bq     = (const float*)d_in[10];
    const float* bk     = (const float*)d_in[11];
    const float* bv     = (const float*)d_in[12];
    const float* bo     = (const float*)d_in[13];
    const float* ffn_w1 = (const float*)d_in[14];
    const float* ffn_b1 = (const float*)d_in[15];
    const float* ffn_w2 = (const float*)d_in[16];
    const float* ffn_b2 = (const float*)d_in[17];
    const float* pw_w   = (const float*)d_in[18];
    const float* pw_b   = (const float*)d_in[19];
    float* out = (float*)d_out;

    float *px, *ph, *pq, *pk, *pv, *pf;
    float2* pst;
    cudaGetSymbolAddress((void**)&px, g_x);
    cudaGetSymbolAddress((void**)&ph, g_h);
    cudaGetSymbolAddress((void**)&pq, g_q);
    cudaGetSymbolAddress((void**)&pk, g_k);
    cudaGetSymbolAddress((void**)&pv, g_v);
    cudaGetSymbolAddress((void**)&pf, g_f1);
    cudaGetSymbolAddress((void**)&pst, g_stats);

    size_t smemRow = (size_t)(2 * LL * DH + DH * DH + 3 * DH + LL) * sizeof(float); // 109120
    size_t smemCol = (size_t)(2 * SS * DH + DH * DH + 3 * DH + SS) * sizeof(float); // 34624
    cudaFuncSetAttribute(attn_kernel, cudaFuncAttributeMaxDynamicSharedMemorySize, 112640);

    dim3 lnBlk(32, 8);
    dim3 gQKV(TT / BM, 6);
    dim3 g192(TT / BM, CC / BN);    // (256, 2)
    dim3 g768(TT / BM, C4 / BN);    // (256, 8)

    embed_kernel<<<TT, CC>>>(tokens, emb, proj_w, proj_b, px);

    for (int i = 0; i < NBLK; i++) {
        for (int dir = 0; dir < 2; dir++) {
            const float* lg = ln_g + (size_t)(i * 3 + dir) * CC;
            const float* lb = ln_b + (size_t)(i * 3 + dir) * CC;
            ln_stats_kernel<<<TT / 8, lnBlk>>>(px, pst);

            size_t woff = ((size_t)i * 2 + dir) * CC * CC;
            size_t boff = ((size_t)i * 2 + dir) * CC;
            qkv_kernel<<<gQKV, 256>>>(px, wq + woff, wk + woff, wv + woff,
                                      bq + boff, bk + boff, bv + boff,
                                      pq, pk, pv, pst, lg, lb);

            if (dir == 0) {
                attn_kernel<<<dim3(BB * SS, HH), 256, smemRow>>>(pq, pk, pv, ph, LL, 0);
            } else {
                attn_kernel<<<dim3(BB * LL, HH), 256, smemCol>>>(pq, pk, pv, ph, SS, 1);
            }

            gemm_kernel<<<g192, 256>>>(ph, wo + woff, bo + boff, px, CC, CC, 0, 1);
        }
        const float* lg = ln_g + (size_t)(i * 3 + 2) * CC;
        const float* lb = ln_b + (size_t)(i * 3 + 2) * CC;
        ln_stats_kernel<<<TT / 8, lnBlk>>>(px, pst);
        gemm_ln_kernel<<<g768, 256>>>(px, ffn_w1 + (size_t)i * C4 * CC, ffn_b1 + (size_t)i * C4,
                                      pf, CC, C4, 3, 0, pst, lg, lb);
        gemm_kernel<<<g192, 256>>>(pf, ffn_w2 + (size_t)i * CC * C4, ffn_b2 + (size_t)i * CC,
                                   px, C4, CC, 0, 1);
    }

    final_kernel<<<TT / 8, lnBlk>>>(px, pw_w, pw_b, out);
}